// round 1
// baseline (speedup 1.0000x reference)
#include <cuda_runtime.h>

#define B_  2
#define L_  2048
#define DK_ 512
#define H_  8
#define DH_ 64
#define BH_ (B_*H_)
#define QT_ (L_/128)   // 16 q-tiles of 128 rows

// Scratch (static __device__ arrays — allocation-free kernel_launch)
__device__ float g_Q[BH_*L_*DH_];            // 8.4 MB
__device__ float g_K[BH_*L_*DH_];            // 8.4 MB
__device__ float g_V[BH_*L_*DH_];            // 8.4 MB
__device__ float g_P[(size_t)BH_*L_*L_];     // 256 MiB: exp(QK^T/sqrt(Lk))
__device__ float g_Dp[BH_*QT_*L_];           // partial column sums (per q-tile)
__device__ float g_Dinv[BH_*L_];             // 1 / column softmax denom

// ---------------------------------------------------------------------------
// Kernel 1: per-head projections.  O[bh, l, e] = sum_d X[b, l, d] * W[h, d, e]
// Tile: 128 rows x 64 cols, 256 threads, 8x4 micro-tile per thread.
// ---------------------------------------------------------------------------
__global__ __launch_bounds__(256) void proj_kernel(
    const float* __restrict__ q_in, const float* __restrict__ k_in,
    const float* __restrict__ v_in, const float* __restrict__ wq,
    const float* __restrict__ wk,  const float* __restrict__ wv)
{
    __shared__ float As[64][128];  // X tile transposed: [d][row]
    __shared__ float Bs[64][64];   // W tile: [d][e]

    const int mat = blockIdx.z;          // 0=Q, 1=K, 2=V
    const int bh  = blockIdx.y;
    const int b   = bh / H_, h = bh % H_;
    const int l0  = blockIdx.x * 128;

    const float* X = (mat == 0) ? q_in : (mat == 1) ? k_in : v_in;
    const float* W = (mat == 0) ? wq   : (mat == 1) ? wk   : wv;
    float*       O = (mat == 0) ? g_Q  : (mat == 1) ? g_K  : g_V;

    const int tid = threadIdx.x;
    const int tx  = tid & 15;            // 16 col-groups of 4
    const int ty  = tid >> 4;            // 16 row-groups of 8

    float acc[8][4];
#pragma unroll
    for (int i = 0; i < 8; ++i)
#pragma unroll
        for (int j = 0; j < 4; ++j) acc[i][j] = 0.f;

    for (int kk = 0; kk < DK_; kk += 64) {
        // X tile [128][64] -> As[d][row]  (8 float4 per thread)
#pragma unroll
        for (int it = 0; it < 8; ++it) {
            int f  = it * 256 + tid;
            int r  = f >> 4;
            int c4 = f & 15;
            float4 v = *(const float4*)(X + ((size_t)(b * L_ + l0 + r)) * DK_ + kk + c4 * 4);
            As[c4*4+0][r] = v.x; As[c4*4+1][r] = v.y;
            As[c4*4+2][r] = v.z; As[c4*4+3][r] = v.w;
        }
        // W tile [64][64] -> Bs (4 float4 per thread)
#pragma unroll
        for (int it = 0; it < 4; ++it) {
            int f  = it * 256 + tid;
            int r  = f >> 4;
            int c4 = f & 15;
            *(float4*)&Bs[r][c4*4] =
                *(const float4*)(W + ((size_t)h * DK_ + kk + r) * DH_ + c4 * 4);
        }
        __syncthreads();
#pragma unroll 16
        for (int d = 0; d < 64; ++d) {
            float4 a0 = *(const float4*)&As[d][ty*8];
            float4 a1 = *(const float4*)&As[d][ty*8+4];
            float4 bv = *(const float4*)&Bs[d][tx*4];
            float a[8] = {a0.x,a0.y,a0.z,a0.w,a1.x,a1.y,a1.z,a1.w};
            float bb[4] = {bv.x,bv.y,bv.z,bv.w};
#pragma unroll
            for (int i = 0; i < 8; ++i)
#pragma unroll
                for (int j = 0; j < 4; ++j) acc[i][j] += a[i] * bb[j];
        }
        __syncthreads();
    }
#pragma unroll
    for (int i = 0; i < 8; ++i) {
        int r = ty * 8 + i;
        float4 v = make_float4(acc[i][0], acc[i][1], acc[i][2], acc[i][3]);
        *(float4*)(O + ((size_t)bh * L_ + l0 + r) * DH_ + tx * 4) = v;
    }
}

// ---------------------------------------------------------------------------
// Kernel 2: P[q,k] = exp(Q·K / sqrt(Lk)), plus per-q-tile column partial sums.
// Tile: 128 q x 64 k per block, full d=64 in one shot.
// ---------------------------------------------------------------------------
__global__ __launch_bounds__(256) void qk_kernel()
{
    __shared__ float As[64][128];  // Q tile transposed: [e][q]
    __shared__ float Bs[64][64];   // K tile transposed: [e][k]

    const int bh = blockIdx.z;
    const int q0 = blockIdx.y * 128;
    const int k0 = blockIdx.x * 64;
    const int tid = threadIdx.x;
    const int tx  = tid & 15;
    const int ty  = tid >> 4;

#pragma unroll
    for (int it = 0; it < 8; ++it) {
        int f = it * 256 + tid;
        int r = f >> 4, c4 = f & 15;
        float4 v = *(const float4*)(g_Q + ((size_t)bh * L_ + q0 + r) * DH_ + c4 * 4);
        As[c4*4+0][r] = v.x; As[c4*4+1][r] = v.y;
        As[c4*4+2][r] = v.z; As[c4*4+3][r] = v.w;
    }
#pragma unroll
    for (int it = 0; it < 4; ++it) {
        int f = it * 256 + tid;
        int r = f >> 4, c4 = f & 15;
        float4 v = *(const float4*)(g_K + ((size_t)bh * L_ + k0 + r) * DH_ + c4 * 4);
        Bs[c4*4+0][r] = v.x; Bs[c4*4+1][r] = v.y;
        Bs[c4*4+2][r] = v.z; Bs[c4*4+3][r] = v.w;
    }
    __syncthreads();

    float acc[8][4];
#pragma unroll
    for (int i = 0; i < 8; ++i)
#pragma unroll
        for (int j = 0; j < 4; ++j) acc[i][j] = 0.f;

#pragma unroll 16
    for (int e = 0; e < 64; ++e) {
        float4 a0 = *(const float4*)&As[e][ty*8];
        float4 a1 = *(const float4*)&As[e][ty*8+4];
        float4 bv = *(const float4*)&Bs[e][tx*4];
        float a[8] = {a0.x,a0.y,a0.z,a0.w,a1.x,a1.y,a1.z,a1.w};
        float bb[4] = {bv.x,bv.y,bv.z,bv.w};
#pragma unroll
        for (int i = 0; i < 8; ++i)
#pragma unroll
            for (int j = 0; j < 4; ++j) acc[i][j] += a[i] * bb[j];
    }

    const float rsc = 0.02209708691207961f;  // 1/sqrt(2048)
    float csum[4] = {0.f, 0.f, 0.f, 0.f};
#pragma unroll
    for (int i = 0; i < 8; ++i) {
        int q = q0 + ty * 8 + i;
        float p0 = __expf(acc[i][0] * rsc);
        float p1 = __expf(acc[i][1] * rsc);
        float p2 = __expf(acc[i][2] * rsc);
        float p3 = __expf(acc[i][3] * rsc);
        csum[0] += p0; csum[1] += p1; csum[2] += p2; csum[3] += p3;
        float4 pv = make_float4(p0, p1, p2, p3);
        *(float4*)(g_P + ((size_t)bh * L_ + q) * L_ + k0 + tx * 4) = pv;
    }

    // Column reduction across the 16 row-groups (reuse As storage).
    __syncthreads();
    float* red = &As[0][0];
    red[ty * 64 + tx * 4 + 0] = csum[0];
    red[ty * 64 + tx * 4 + 1] = csum[1];
    red[ty * 64 + tx * 4 + 2] = csum[2];
    red[ty * 64 + tx * 4 + 3] = csum[3];
    __syncthreads();
    if (tid < 64) {
        float s = 0.f;
#pragma unroll
        for (int i = 0; i < 16; ++i) s += red[i * 64 + tid];
        g_Dp[((size_t)bh * QT_ + blockIdx.y) * L_ + k0 + tid] = s;
    }
}

// ---------------------------------------------------------------------------
// Kernel 2b: reduce partial sums -> 1/D[k]  (deterministic, no atomics)
// ---------------------------------------------------------------------------
__global__ __launch_bounds__(256) void dred_kernel()
{
    int g  = blockIdx.x * 256 + threadIdx.x;  // < BH_*L_
    int bh = g / L_;
    int k  = g % L_;
    float s = 0.f;
#pragma unroll
    for (int qt = 0; qt < QT_; ++qt) s += g_Dp[((size_t)bh * QT_ + qt) * L_ + k];
    g_Dinv[g] = 1.0f / s;
}

// ---------------------------------------------------------------------------
// Kernel 3: out[b, q, h*64+e] = sum_k P[q,k] * (V[k,e] / D[k])
// Tile: 128 q x 64 e, loop over k in steps of 64.
// ---------------------------------------------------------------------------
__global__ __launch_bounds__(256) void pv_kernel(float* __restrict__ out)
{
    __shared__ float As[64][128];  // P tile transposed: [k][q]
    __shared__ float Bs[64][64];   // (V/D) tile: [k][e]

    const int bh = blockIdx.y;
    const int b  = bh / H_, h = bh % H_;
    const int q0 = blockIdx.x * 128;
    const int tid = threadIdx.x;
    const int tx  = tid & 15;
    const int ty  = tid >> 4;

    float acc[8][4];
#pragma unroll
    for (int i = 0; i < 8; ++i)
#pragma unroll
        for (int j = 0; j < 4; ++j) acc[i][j] = 0.f;

    for (int k0 = 0; k0 < L_; k0 += 64) {
#pragma unroll
        for (int it = 0; it < 8; ++it) {
            int f = it * 256 + tid;
            int r = f >> 4, c4 = f & 15;
            float4 v = *(const float4*)(g_P + ((size_t)bh * L_ + q0 + r) * L_ + k0 + c4 * 4);
            As[c4*4+0][r] = v.x; As[c4*4+1][r] = v.y;
            As[c4*4+2][r] = v.z; As[c4*4+3][r] = v.w;
        }
#pragma unroll
        for (int it = 0; it < 4; ++it) {
            int f = it * 256 + tid;
            int r = f >> 4, c4 = f & 15;
            float dinv = g_Dinv[bh * L_ + k0 + r];
            float4 v = *(const float4*)(g_V + ((size_t)bh * L_ + k0 + r) * DH_ + c4 * 4);
            v.x *= dinv; v.y *= dinv; v.z *= dinv; v.w *= dinv;
            *(float4*)&Bs[r][c4*4] = v;
        }
        __syncthreads();
#pragma unroll 16
        for (int d = 0; d < 64; ++d) {
            float4 a0 = *(const float4*)&As[d][ty*8];
            float4 a1 = *(const float4*)&As[d][ty*8+4];
            float4 bv = *(const float4*)&Bs[d][tx*4];
            float a[8] = {a0.x,a0.y,a0.z,a0.w,a1.x,a1.y,a1.z,a1.w};
            float bb[4] = {bv.x,bv.y,bv.z,bv.w};
#pragma unroll
            for (int i = 0; i < 8; ++i)
#pragma unroll
                for (int j = 0; j < 4; ++j) acc[i][j] += a[i] * bb[j];
        }
        __syncthreads();
    }
#pragma unroll
    for (int i = 0; i < 8; ++i) {
        int q = q0 + ty * 8 + i;
        float4 v = make_float4(acc[i][0], acc[i][1], acc[i][2], acc[i][3]);
        *(float4*)(out + ((size_t)b * L_ + q) * (H_ * DH_) + h * DH_ + tx * 4) = v;
    }
}

// ---------------------------------------------------------------------------
extern "C" void kernel_launch(void* const* d_in, const int* in_sizes, int n_in,
                              void* d_out, int out_size)
{
    // metadata order: keys, queries, values, WQ, WK, WV
    const float* keys    = (const float*)d_in[0];
    const float* queries = (const float*)d_in[1];
    const float* values  = (const float*)d_in[2];
    const float* WQ      = (const float*)d_in[3];
    const float* WK      = (const float*)d_in[4];
    const float* WV      = (const float*)d_in[5];
    float* out = (float*)d_out;

    proj_kernel<<<dim3(L_ / 128, BH_, 3), 256>>>(queries, keys, values, WQ, WK, WV);
    qk_kernel<<<dim3(L_ / 64, L_ / 128, BH_), 256>>>();
    dred_kernel<<<(BH_ * L_) / 256, 256>>>();
    pv_kernel<<<dim3(L_ / 128, BH_), 256>>>(out);
}

// round 2
// speedup vs baseline: 3.1655x; 3.1655x over previous
#include <cuda_runtime.h>
#include <cstdint>

#define B_  2
#define L_  2048
#define DK_ 512
#define H_  8
#define DH_ 64
#define BH_ (B_*H_)
#define QB_ (L_/128)   // 16 q-blocks
#define STR 68         // smem row stride in floats (≡4 mod 32 → conflict-free frags)

// ---- device scratch (allocation-free) ----
__device__ float g_Q[BH_*L_*DH_];
__device__ float g_K[BH_*L_*DH_];
__device__ float g_V[BH_*L_*DH_];
__device__ float g_Wt[3*H_*DH_*DK_];        // [mat][h][e][d]  (W transposed)
__device__ float g_Vt[BH_*DH_*L_];          // [bh][e][k] = V[k][e] * Dinv[k]
__device__ float g_P[(size_t)BH_*L_*L_];    // exp(QK^T/sqrt(Lk)), 256 MiB
__device__ float g_Dp[BH_*QB_*L_];          // per-qblock column partial sums
__device__ float g_Dinv[BH_*L_];

// ---- helpers ----
__device__ __forceinline__ float cvt_tf32(float x) {
    uint32_t r; asm("cvt.rna.tf32.f32 %0, %1;" : "=r"(r) : "f"(x));
    return __uint_as_float(r);
}
__device__ __forceinline__ float4 cvt4(float4 v) {
    return make_float4(cvt_tf32(v.x), cvt_tf32(v.y), cvt_tf32(v.z), cvt_tf32(v.w));
}
__device__ __forceinline__ void mma_tf32(float* d, float a0, float a1, float a2, float a3,
                                         float b0, float b1) {
    asm volatile("mma.sync.aligned.m16n8k8.row.col.f32.tf32.tf32.f32 "
                 "{%0,%1,%2,%3}, {%4,%5,%6,%7}, {%8,%9}, {%0,%1,%2,%3};"
                 : "+f"(d[0]), "+f"(d[1]), "+f"(d[2]), "+f"(d[3])
                 : "r"(__float_as_uint(a0)), "r"(__float_as_uint(a1)),
                   "r"(__float_as_uint(a2)), "r"(__float_as_uint(a3)),
                   "r"(__float_as_uint(b0)), "r"(__float_as_uint(b1)));
}

// ---------------------------------------------------------------------------
// W transpose: W[h][d][e] -> g_Wt[mat*H+h][e][d]
// ---------------------------------------------------------------------------
__global__ __launch_bounds__(256) void wprep_kernel(
    const float* __restrict__ wq, const float* __restrict__ wk,
    const float* __restrict__ wv)
{
    __shared__ float t[32][33];
    const int mh  = blockIdx.z;          // mat*H + h
    const int mat = mh / H_, h = mh % H_;
    const float* W = (mat == 0) ? wq : (mat == 1) ? wk : wv;
    const int d0 = blockIdx.x * 32, e0 = blockIdx.y * 32;
    const int tx = threadIdx.x & 31, ty = threadIdx.x >> 5;
#pragma unroll
    for (int i = 0; i < 32; i += 8)
        t[ty + i][tx] = W[((size_t)h * DK_ + d0 + ty + i) * DH_ + e0 + tx];
    __syncthreads();
#pragma unroll
    for (int i = 0; i < 32; i += 8)
        g_Wt[((size_t)mh * DH_ + e0 + ty + i) * DK_ + d0 + tx] = t[tx][ty + i];
}

// ---------------------------------------------------------------------------
// Projections via tf32 mma: O[128 l x 64 e] = X[128 x 512] * W[512 x 64]
// 128 threads, warps 2x2, warp tile 64x32 (mt=4, nt=4).
// ---------------------------------------------------------------------------
__global__ __launch_bounds__(128) void proj_kernel(
    const float* __restrict__ q_in, const float* __restrict__ k_in,
    const float* __restrict__ v_in)
{
    extern __shared__ float sm[];
    float* Xs = sm;             // [128][STR]
    float* Ws = sm + 128*STR;   // [64][STR]   (W^T: [e][d])

    const int mat = blockIdx.z, bh = blockIdx.y, l0 = blockIdx.x * 128;
    const int b = bh / H_, h = bh % H_;
    const float* X  = (mat == 0) ? q_in : (mat == 1) ? k_in : v_in;
    const float* Wt = g_Wt + ((size_t)(mat * H_ + h)) * DH_ * DK_;
    float*       O  = (mat == 0) ? g_Q : (mat == 1) ? g_K : g_V;

    const int tid = threadIdx.x, lane = tid & 31, wid = tid >> 5;
    const int wm = wid >> 1, wn = wid & 1;
    const int grp = lane >> 2, cp = lane & 3;

    float acc[4][4][4];
#pragma unroll
    for (int i = 0; i < 4; ++i)
#pragma unroll
        for (int j = 0; j < 4; ++j)
#pragma unroll
            for (int c = 0; c < 4; ++c) acc[i][j][c] = 0.f;

    for (int d0 = 0; d0 < DK_; d0 += 64) {
#pragma unroll
        for (int it = 0; it < 16; ++it) {
            int f = it * 128 + tid;
            int r = f >> 4, c4 = f & 15;
            float4 v = *(const float4*)(X + ((size_t)(b * L_ + l0 + r)) * DK_ + d0 + c4 * 4);
            *(float4*)(Xs + r * STR + c4 * 4) = cvt4(v);
        }
#pragma unroll
        for (int it = 0; it < 8; ++it) {
            int f = it * 128 + tid;
            int r = f >> 4, c4 = f & 15;
            float4 v = *(const float4*)(Wt + (size_t)r * DK_ + d0 + c4 * 4);
            *(float4*)(Ws + r * STR + c4 * 4) = cvt4(v);
        }
        __syncthreads();
#pragma unroll
        for (int ks = 0; ks < 8; ++ks) {
            float a[4][4];
#pragma unroll
            for (int mt = 0; mt < 4; ++mt) {
                const float* base = Xs + (wm*64 + mt*16 + grp) * STR + ks*8 + cp;
                a[mt][0] = base[0];       a[mt][2] = base[4];
                a[mt][1] = base[8*STR];   a[mt][3] = base[8*STR + 4];
            }
            float bf[4][2];
#pragma unroll
            for (int nt = 0; nt < 4; ++nt) {
                const float* base = Ws + (wn*32 + nt*8 + grp) * STR + ks*8 + cp;
                bf[nt][0] = base[0];      bf[nt][1] = base[4];
            }
#pragma unroll
            for (int mt = 0; mt < 4; ++mt)
#pragma unroll
                for (int nt = 0; nt < 4; ++nt)
                    mma_tf32(acc[mt][nt], a[mt][0], a[mt][1], a[mt][2], a[mt][3],
                             bf[nt][0], bf[nt][1]);
        }
        __syncthreads();
    }
#pragma unroll
    for (int mt = 0; mt < 4; ++mt) {
        int l = l0 + wm*64 + mt*16 + grp;
#pragma unroll
        for (int nt = 0; nt < 4; ++nt) {
            int e = wn*32 + nt*8 + cp*2;
            *(float2*)(O + ((size_t)bh*L_ + l)*DH_ + e)     = make_float2(acc[mt][nt][0], acc[mt][nt][1]);
            *(float2*)(O + ((size_t)bh*L_ + l + 8)*DH_ + e) = make_float2(acc[mt][nt][2], acc[mt][nt][3]);
        }
    }
}

// ---------------------------------------------------------------------------
// QK^T via tf32 mma + exp + column partial sums.
// 256 threads, warps 2x4, warp tile 64x32 (mt=4, nt=4). Block tile 128q x 128k.
// ---------------------------------------------------------------------------
__global__ __launch_bounds__(256) void qk_kernel()
{
    extern __shared__ float sm[];
    float* Qs = sm;                 // [128][STR]
    float* Ks = sm + 128*STR;       // [128][STR]
    float* Cs = sm + 2*128*STR;     // [2][128] column sums

    const int bh = blockIdx.z, qb = blockIdx.y, kb = blockIdx.x;
    const int q0 = qb * 128, k0 = kb * 128;
    const int tid = threadIdx.x, lane = tid & 31, wid = tid >> 5;
    const int wm = wid >> 2, wn = wid & 3;
    const int grp = lane >> 2, cp = lane & 3;

#pragma unroll
    for (int it = 0; it < 8; ++it) {
        int f = it * 256 + tid;
        int r = f >> 4, c4 = f & 15;
        float4 v = *(const float4*)(g_Q + ((size_t)bh*L_ + q0 + r)*DH_ + c4*4);
        *(float4*)(Qs + r*STR + c4*4) = cvt4(v);
        float4 w = *(const float4*)(g_K + ((size_t)bh*L_ + k0 + r)*DH_ + c4*4);
        *(float4*)(Ks + r*STR + c4*4) = cvt4(w);
    }
    __syncthreads();

    float acc[4][4][4];
#pragma unroll
    for (int i = 0; i < 4; ++i)
#pragma unroll
        for (int j = 0; j < 4; ++j)
#pragma unroll
            for (int c = 0; c < 4; ++c) acc[i][j][c] = 0.f;

#pragma unroll
    for (int ks = 0; ks < 8; ++ks) {
        float a[4][4];
#pragma unroll
        for (int mt = 0; mt < 4; ++mt) {
            const float* base = Qs + (wm*64 + mt*16 + grp) * STR + ks*8 + cp;
            a[mt][0] = base[0];      a[mt][2] = base[4];
            a[mt][1] = base[8*STR];  a[mt][3] = base[8*STR + 4];
        }
        float bf[4][2];
#pragma unroll
        for (int nt = 0; nt < 4; ++nt) {
            const float* base = Ks + (wn*32 + nt*8 + grp) * STR + ks*8 + cp;
            bf[nt][0] = base[0];     bf[nt][1] = base[4];
        }
#pragma unroll
        for (int mt = 0; mt < 4; ++mt)
#pragma unroll
            for (int nt = 0; nt < 4; ++nt)
                mma_tf32(acc[mt][nt], a[mt][0], a[mt][1], a[mt][2], a[mt][3],
                         bf[nt][0], bf[nt][1]);
    }

    const float rsc = 0.02209708691207961f;  // 1/sqrt(2048)
    float cs0[4] = {0,0,0,0}, cs1[4] = {0,0,0,0};
#pragma unroll
    for (int mt = 0; mt < 4; ++mt) {
        int q = q0 + wm*64 + mt*16 + grp;
#pragma unroll
        for (int nt = 0; nt < 4; ++nt) {
            int k = k0 + wn*32 + nt*8 + cp*2;
            float p0 = __expf(acc[mt][nt][0] * rsc);
            float p1 = __expf(acc[mt][nt][1] * rsc);
            float p2 = __expf(acc[mt][nt][2] * rsc);
            float p3 = __expf(acc[mt][nt][3] * rsc);
            cs0[nt] += p0 + p2;  cs1[nt] += p1 + p3;
            *(float2*)(g_P + ((size_t)bh*L_ + q)*L_ + k)     = make_float2(p0, p1);
            *(float2*)(g_P + ((size_t)bh*L_ + q + 8)*L_ + k) = make_float2(p2, p3);
        }
    }
    // reduce over grp (8 row-groups) within warp
#pragma unroll
    for (int nt = 0; nt < 4; ++nt) {
        cs0[nt] += __shfl_xor_sync(0xffffffffu, cs0[nt], 4);
        cs0[nt] += __shfl_xor_sync(0xffffffffu, cs0[nt], 8);
        cs0[nt] += __shfl_xor_sync(0xffffffffu, cs0[nt], 16);
        cs1[nt] += __shfl_xor_sync(0xffffffffu, cs1[nt], 4);
        cs1[nt] += __shfl_xor_sync(0xffffffffu, cs1[nt], 8);
        cs1[nt] += __shfl_xor_sync(0xffffffffu, cs1[nt], 16);
    }
    if (lane < 4) {
#pragma unroll
        for (int nt = 0; nt < 4; ++nt) {
            Cs[wm*128 + wn*32 + nt*8 + lane*2]     = cs0[nt];
            Cs[wm*128 + wn*32 + nt*8 + lane*2 + 1] = cs1[nt];
        }
    }
    __syncthreads();
    if (tid < 128)
        g_Dp[((size_t)bh*QB_ + qb)*L_ + k0 + tid] = Cs[tid] + Cs[128 + tid];
}

// ---------------------------------------------------------------------------
// Reduce partial column sums -> 1/D[k]
// ---------------------------------------------------------------------------
__global__ __launch_bounds__(256) void dred_kernel()
{
    int g  = blockIdx.x * 256 + threadIdx.x;
    int bh = g / L_, k = g % L_;
    float s = 0.f;
#pragma unroll
    for (int qt = 0; qt < QB_; ++qt) s += g_Dp[((size_t)bh*QB_ + qt)*L_ + k];
    g_Dinv[g] = 1.0f / s;
}

// ---------------------------------------------------------------------------
// V transpose + scale: g_Vt[bh][e][k] = V[bh][k][e] * Dinv[bh][k]
// ---------------------------------------------------------------------------
__global__ __launch_bounds__(256) void vprep_kernel()
{
    __shared__ float t[32][33];
    const int bh = blockIdx.z;
    const int k0 = blockIdx.x * 32, e0 = blockIdx.y * 32;
    const int tx = threadIdx.x & 31, ty = threadIdx.x >> 5;
#pragma unroll
    for (int i = 0; i < 32; i += 8) {
        int k = k0 + ty + i;
        t[ty + i][tx] = g_V[((size_t)bh*L_ + k)*DH_ + e0 + tx] * g_Dinv[bh*L_ + k];
    }
    __syncthreads();
#pragma unroll
    for (int i = 0; i < 32; i += 8)
        g_Vt[((size_t)bh*DH_ + e0 + ty + i)*L_ + k0 + tx] = t[tx][ty + i];
}

// ---------------------------------------------------------------------------
// PV via tf32 mma: out[128q x 64e] = P[128 x 2048] * Vt^T
// 128 threads, warps 2x2, warp tile 64x32 (mt=4, nt=4), k-chunks of 64.
// ---------------------------------------------------------------------------
__global__ __launch_bounds__(128) void pv_kernel(float* __restrict__ out)
{
    extern __shared__ float sm[];
    float* Ps = sm;             // [128][STR]
    float* Vs = sm + 128*STR;   // [64][STR]   (Vt: [e][k])

    const int bh = blockIdx.y, q0 = blockIdx.x * 128;
    const int b = bh / H_, h = bh % H_;
    const int tid = threadIdx.x, lane = tid & 31, wid = tid >> 5;
    const int wm = wid >> 1, wn = wid & 1;
    const int grp = lane >> 2, cp = lane & 3;

    float acc[4][4][4];
#pragma unroll
    for (int i = 0; i < 4; ++i)
#pragma unroll
        for (int j = 0; j < 4; ++j)
#pragma unroll
            for (int c = 0; c < 4; ++c) acc[i][j][c] = 0.f;

    for (int k0 = 0; k0 < L_; k0 += 64) {
#pragma unroll
        for (int it = 0; it < 16; ++it) {
            int f = it * 128 + tid;
            int r = f >> 4, c4 = f & 15;
            float4 v = *(const float4*)(g_P + ((size_t)bh*L_ + q0 + r)*L_ + k0 + c4*4);
            *(float4*)(Ps + r*STR + c4*4) = cvt4(v);
        }
#pragma unroll
        for (int it = 0; it < 8; ++it) {
            int f = it * 128 + tid;
            int r = f >> 4, c4 = f & 15;
            float4 v = *(const float4*)(g_Vt + ((size_t)bh*DH_ + r)*L_ + k0 + c4*4);
            *(float4*)(Vs + r*STR + c4*4) = cvt4(v);
        }
        __syncthreads();
#pragma unroll
        for (int ks = 0; ks < 8; ++ks) {
            float a[4][4];
#pragma unroll
            for (int mt = 0; mt < 4; ++mt) {
                const float* base = Ps + (wm*64 + mt*16 + grp) * STR + ks*8 + cp;
                a[mt][0] = base[0];      a[mt][2] = base[4];
                a[mt][1] = base[8*STR];  a[mt][3] = base[8*STR + 4];
            }
            float bf[4][2];
#pragma unroll
            for (int nt = 0; nt < 4; ++nt) {
                const float* base = Vs + (wn*32 + nt*8 + grp) * STR + ks*8 + cp;
                bf[nt][0] = base[0];     bf[nt][1] = base[4];
            }
#pragma unroll
            for (int mt = 0; mt < 4; ++mt)
#pragma unroll
                for (int nt = 0; nt < 4; ++nt)
                    mma_tf32(acc[mt][nt], a[mt][0], a[mt][1], a[mt][2], a[mt][3],
                             bf[nt][0], bf[nt][1]);
        }
        __syncthreads();
    }
#pragma unroll
    for (int mt = 0; mt < 4; ++mt) {
        int q = q0 + wm*64 + mt*16 + grp;
#pragma unroll
        for (int nt = 0; nt < 4; ++nt) {
            int e = wn*32 + nt*8 + cp*2;
            *(float2*)(out + ((size_t)b*L_ + q)*(H_*DH_) + h*DH_ + e) =
                make_float2(acc[mt][nt][0], acc[mt][nt][1]);
            *(float2*)(out + ((size_t)b*L_ + q + 8)*(H_*DH_) + h*DH_ + e) =
                make_float2(acc[mt][nt][2], acc[mt][nt][3]);
        }
    }
}

// ---------------------------------------------------------------------------
extern "C" void kernel_launch(void* const* d_in, const int* in_sizes, int n_in,
                              void* d_out, int out_size)
{
    const float* keys    = (const float*)d_in[0];
    const float* queries = (const float*)d_in[1];
    const float* values  = (const float*)d_in[2];
    const float* WQ      = (const float*)d_in[3];
    const float* WK      = (const float*)d_in[4];
    const float* WV      = (const float*)d_in[5];
    float* out = (float*)d_out;

    const int QK_SMEM = (2*128*STR + 256) * 4;   // 70656
    const int PP_SMEM = (192*STR) * 4;           // 52224

    cudaFuncSetAttribute(qk_kernel,   cudaFuncAttributeMaxDynamicSharedMemorySize, QK_SMEM);
    cudaFuncSetAttribute(proj_kernel, cudaFuncAttributeMaxDynamicSharedMemorySize, PP_SMEM);
    cudaFuncSetAttribute(pv_kernel,   cudaFuncAttributeMaxDynamicSharedMemorySize, PP_SMEM);

    wprep_kernel<<<dim3(DK_/32, DH_/32, 24), 256>>>(WQ, WK, WV);
    proj_kernel<<<dim3(L_/128, BH_, 3), 128, PP_SMEM>>>(queries, keys, values);
    qk_kernel<<<dim3(L_/128, L_/128, BH_), 256, QK_SMEM>>>();
    dred_kernel<<<(BH_*L_)/256, 256>>>();
    vprep_kernel<<<dim3(L_/32, DH_/32, BH_), 256>>>();
    pv_kernel<<<dim3(L_/128, BH_), 128, PP_SMEM>>>(out);
}